// round 16
// baseline (speedup 1.0000x reference)
#include <cuda_runtime.h>
#include <cuda_bf16.h>

// Shapes (fixed per reference)
#define S_DIM   64
#define C_DIM   384
#define HW      3136          // 56*56
#define HW4     784           // HW/4 (float4 quads per channel plane)
#define CHW     (C_DIM * HW)  // 1204224 floats per frame
#define S_TOP   16
#define CNUM    48            // C_DIM / 8

#define SEG     8             // frames per conv segment (R13 best config)
#define NSEG    (S_DIM / SEG) // 8
#define NQUADS  (C_DIM * HW4) // 301056 (c, quad) tasks
#define CONV_T  256           // conv block size (R13 best config)
#define BLK_PER_SEG (NQUADS / CONV_T)  // 1176, exact

// Scratch (no device allocation allowed)
__device__ float g_xg[S_DIM * C_DIM];     // per-frame, per-channel means
__device__ float g_convk[C_DIM * 3];      // per-channel temporal kernel (softmaxed)
__device__ int   g_flag;                  // convk-ready flag (reset per call)

__device__ __forceinline__ void griddep_launch() {
    asm volatile("griddepcontrol.launch_dependents;");
}
__device__ __forceinline__ void griddep_wait() {
    asm volatile("griddepcontrol.wait;" ::: "memory");
}
__device__ __forceinline__ int ld_acquire(const int* p) {
    int v;
    asm volatile("ld.acquire.gpu.b32 %0, [%1];" : "=r"(v) : "l"(p) : "memory");
    return v;
}
__device__ __forceinline__ void st_release(int* p, int v) {
    asm volatile("st.release.gpu.b32 [%0], %1;" :: "l"(p), "r"(v) : "memory");
}

// ---------------------------------------------------------------------------
// Kernel 1: global average pool. One block per (s,c) plane of 3136 floats.
// ---------------------------------------------------------------------------
__global__ void pool_kernel(const float* __restrict__ x) {
    griddep_launch();
    int plane = blockIdx.x;                 // = s*C_DIM + c
    const float4* p = reinterpret_cast<const float4*>(x + (size_t)plane * HW);
    float sum = 0.f;
    for (int i = threadIdx.x; i < HW4; i += blockDim.x) {
        float4 v = __ldcs(p + i);           // streaming read: evict-first
        sum += (v.x + v.y) + (v.z + v.w);
    }
    #pragma unroll
    for (int off = 16; off > 0; off >>= 1)
        sum += __shfl_down_sync(0xFFFFFFFFu, sum, off);
    __shared__ float warp_sums[4];
    int lane = threadIdx.x & 31, wid = threadIdx.x >> 5;
    if (lane == 0) warp_sums[wid] = sum;
    __syncthreads();
    if (threadIdx.x == 0) {
        float t = warp_sums[0] + warp_sums[1] + warp_sums[2] + warp_sums[3];
        g_xg[plane] = t * (1.0f / (float)HW);
    }
}

// ---------------------------------------------------------------------------
// Kernel 2 (fused conv + in-grid MLP): PDL secondary of pool.
// All blocks batch their x loads pre-wait. Post-wait, block 0 computes the
// scores -> stable top-16 -> per-channel MLP -> softmax -> g_convk, then
// release-stores g_flag. Other blocks acquire-spin (loads already in
// flight), then run the depthwise temporal conv. seg is the FAST block dim
// (same-wave halo -> L2). Writes __stcs.
// ---------------------------------------------------------------------------
__global__ void __launch_bounds__(CONV_T)
conv_kernel(const float* __restrict__ x, float* __restrict__ out,
            const float* __restrict__ w_lin,
            const float* __restrict__ w1,
            const float* __restrict__ bn_gamma,
            const float* __restrict__ bn_beta,
            const float* __restrict__ bn_mean,
            const float* __restrict__ bn_var,
            const float* __restrict__ w2) {
    int b     = blockIdx.x;
    int seg   = b & (NSEG - 1);              // fast dim: waves mix all segments
    int chunk = b >> 3;                      // 0 .. BLK_PER_SEG-1
    int task  = chunk * CONV_T + threadIdx.x;   // < NQUADS (exact multiple)
    int c = task / HW4;
    int q = task - c * HW4;
    size_t base = (size_t)c * HW + (size_t)q * 4;   // float index, 16B aligned
    int t0 = seg * SEG;
    int t  = threadIdx.x;
    bool leader = (b == 0);

    // channel shift: c<48 -> read x[s+1]; 48<=c<96 -> x[s-1]; else x[s]
    int d = (c < CNUM) ? 1 : ((c < 2 * CNUM) ? -1 : 0);

    // leader-only smem (small; allocated in all blocks, used by block 0)
    __shared__ float s_wlin[C_DIM];
    __shared__ float s_w1[2 * S_TOP * S_TOP];   // 512
    __shared__ float s_w2[3 * 2 * S_TOP];       // 96
    __shared__ float s_scale[2 * S_TOP], s_mean[2 * S_TOP], s_beta[2 * S_TOP];
    __shared__ float sc[S_DIM];
    __shared__ int   sflag[S_DIM];
    __shared__ int   idx[S_TOP];

    // --- pre-wait: leader prefetches weights (independent of pool) ---
    if (leader) {
        for (int i = t; i < C_DIM; i += CONV_T) s_wlin[i] = w_lin[i];
        for (int i = t; i < 2 * S_TOP * S_TOP; i += CONV_T) s_w1[i] = w1[i];
        if (t < 3 * 2 * S_TOP) s_w2[t] = w2[t];
        if (t < 2 * S_TOP) {
            s_scale[t] = bn_gamma[t] * rsqrtf(bn_var[t] + 1e-5f);
            s_mean[t]  = bn_mean[t];
            s_beta[t]  = bn_beta[t];
        }
    }

    const float4 zero4 = make_float4(0.f, 0.f, 0.f, 0.f);

    // --- pre-wait: batch load t0-1 .. t0+SEG (SEG+2 independent LDG.128) ---
    float4 v[SEG + 2];
    #pragma unroll
    for (int i = 0; i < SEG + 2; i++) {
        int tt = t0 - 1 + i;
        int ts = tt + d;
        v[i] = ((unsigned)tt < (unsigned)S_DIM && (unsigned)ts < (unsigned)S_DIM)
             ? *reinterpret_cast<const float4*>(x + (size_t)ts * CHW + base)
             : zero4;
    }

    griddep_wait();                          // pool complete: g_xg visible

    if (leader) {
        __syncthreads();                     // weights prefetched
        int lane = t & 31;
        int wid  = t >> 5;                   // 0..7

        // scores: one warp per frame, 8 rounds
        #pragma unroll
        for (int r = 0; r < S_DIM / 8; r++) {
            int s = wid + r * 8;
            const float* row = g_xg + s * C_DIM;
            float acc = 0.f;
            #pragma unroll
            for (int j = 0; j < C_DIM / 32; j++) {
                int cc = lane + j * 32;
                acc = fmaf(row[cc], s_wlin[cc], acc);
            }
            #pragma unroll
            for (int off = 16; off > 0; off >>= 1)
                acc += __shfl_down_sync(0xFFFFFFFFu, acc, off);
            if (lane == 0) sc[s] = acc;
        }
        __syncthreads();

        // stable rank
        if (t < S_DIM) {
            float si = sc[t];
            int rank = 0;
            #pragma unroll 8
            for (int j = 0; j < S_DIM; j++) {
                float sj = sc[j];
                rank += (sj > si || (sj == si && j < t)) ? 1 : 0;
            }
            sflag[t] = (rank < S_TOP) ? 1 : 0;
        }
        __syncthreads();
        if (t == 0) {
            int n = 0;
            for (int i = 0; i < S_DIM; i++)
                if (sflag[i] && n < S_TOP) idx[n++] = i;
        }
        __syncthreads();

        // per-channel MLP: 256 threads cover 384 channels in 2 passes
        for (int cc = t; cc < C_DIM; cc += CONV_T) {
            float sls[S_TOP];
            #pragma unroll
            for (int j = 0; j < S_TOP; j++) sls[j] = g_xg[idx[j] * C_DIM + cc];

            float l0 = 0.f, l1 = 0.f, l2 = 0.f;
            #pragma unroll 4
            for (int k = 0; k < 2 * S_TOP; k++) {
                float acc = 0.f;
                const float* w1row = s_w1 + k * S_TOP;
                #pragma unroll
                for (int j = 0; j < S_TOP; j++) acc = fmaf(sls[j], w1row[j], acc);
                acc = fmaf(acc - s_mean[k], s_scale[k], s_beta[k]);   // BN eval
                acc = fmaxf(acc, 0.f);                                // ReLU
                l0 = fmaf(acc, s_w2[0 * 2 * S_TOP + k], l0);
                l1 = fmaf(acc, s_w2[1 * 2 * S_TOP + k], l1);
                l2 = fmaf(acc, s_w2[2 * 2 * S_TOP + k], l2);
            }
            float mx = fmaxf(l0, fmaxf(l1, l2));
            float e0 = __expf(l0 - mx), e1 = __expf(l1 - mx), e2 = __expf(l2 - mx);
            float inv = 1.0f / (e0 + e1 + e2);
            g_convk[cc * 3 + 0] = e0 * inv;
            g_convk[cc * 3 + 1] = e1 * inv;
            g_convk[cc * 3 + 2] = e2 * inv;
        }
        __syncthreads();
        if (t == 0) {
            __threadfence();
            st_release(&g_flag, 1);
        }
    } else {
        // spin until convk ready (loads above already in flight)
        if (t == 0) {
            while (ld_acquire(&g_flag) == 0) __nanosleep(64);
        }
        __syncthreads();
    }

    float k0 = g_convk[c * 3 + 0];
    float k1 = g_convk[c * 3 + 1];
    float k2 = g_convk[c * 3 + 2];

    // FMA + store burst
    #pragma unroll
    for (int i = 0; i < SEG; i++) {
        float4 a = v[i], bb = v[i + 1], cc4 = v[i + 2];
        float4 o;
        o.x = fmaf(k0, a.x, fmaf(k1, bb.x, k2 * cc4.x));
        o.y = fmaf(k0, a.y, fmaf(k1, bb.y, k2 * cc4.y));
        o.z = fmaf(k0, a.z, fmaf(k1, bb.z, k2 * cc4.z));
        o.w = fmaf(k0, a.w, fmaf(k1, bb.w, k2 * cc4.w));
        __stcs(reinterpret_cast<float4*>(out + (size_t)(t0 + i) * CHW + base), o);
    }
}

// ---------------------------------------------------------------------------
extern "C" void kernel_launch(void* const* d_in, const int* in_sizes, int n_in,
                              void* d_out, int out_size) {
    const float* x        = (const float*)d_in[0];
    const float* w_lin    = (const float*)d_in[1];
    const float* w1       = (const float*)d_in[2];
    const float* bn_gamma = (const float*)d_in[3];
    const float* bn_beta  = (const float*)d_in[4];
    const float* bn_mean  = (const float*)d_in[5];
    const float* bn_var   = (const float*)d_in[6];
    const float* w2       = (const float*)d_in[7];
    float* out            = (float*)d_out;

    // reset convk-ready flag (async, graph-capturable, no alloc)
    void* flag_ptr = nullptr;
    cudaGetSymbolAddress(&flag_ptr, g_flag);
    cudaMemsetAsync(flag_ptr, 0, sizeof(int));

    pool_kernel<<<S_DIM * C_DIM, 128>>>(x);

    // conv (with fused MLP in block 0): PDL secondary of pool
    {
        cudaLaunchConfig_t cfg = {};
        cfg.gridDim  = dim3(NSEG * BLK_PER_SEG, 1, 1);
        cfg.blockDim = dim3(CONV_T, 1, 1);
        cudaLaunchAttribute attr[1];
        attr[0].id = cudaLaunchAttributeProgrammaticStreamSerialization;
        attr[0].val.programmaticStreamSerializationAllowed = 1;
        cfg.attrs = attr;
        cfg.numAttrs = 1;
        cudaLaunchKernelEx(&cfg, conv_kernel, x, out,
                           w_lin, w1, bn_gamma, bn_beta, bn_mean, bn_var, w2);
    }
}